// round 11
// baseline (speedup 1.0000x reference)
#include <cuda_runtime.h>
#include <cuda_fp16.h>
#include <cstdint>

#define B_ 8
#define P_ 75
#define HW_ 196
#define C_ 384
#define H_ 6
#define D_ 64
#define M_ 25
#define SCALE_ 0.125f

// smem byte map
#define SM_KV   0          // 208 rows x 128B fp16, SW128 swizzled
#define SM_Q    26624      // 32 rows x 128B fp16, swizzled
#define SM_EXP  30720      // 32 rows x 432B (216 fp16, padded stride; w-permuted cols)
#define SM_PSUM 44544      // 32 rows x 8 f32 partials
#define SMEM_BYTES 45568

#define EXSTR 432

static __device__ __forceinline__ uint32_t kvoff(int r, int c) {   // 128B-row SW128
    return (uint32_t)(r * 128 + ((c) ^ ((r & 7) << 4)));
}
static __device__ __forceinline__ uint32_t smem_u32(const void* p) {
    uint32_t a;
    asm("{ .reg .u64 t; cvta.to.shared.u64 t, %1; cvt.u32.u64 %0, t; }" : "=r"(a) : "l"(p));
    return a;
}
static __device__ __forceinline__ void ldsm4(uint32_t* r, uint32_t a) {
    asm volatile("ldmatrix.sync.aligned.m8n8.x4.shared.b16 {%0,%1,%2,%3}, [%4];"
        : "=r"(r[0]), "=r"(r[1]), "=r"(r[2]), "=r"(r[3]) : "r"(a));
}
static __device__ __forceinline__ void ldsm4t(uint32_t* r, uint32_t a) {
    asm volatile("ldmatrix.sync.aligned.m8n8.x4.trans.shared.b16 {%0,%1,%2,%3}, [%4];"
        : "=r"(r[0]), "=r"(r[1]), "=r"(r[2]), "=r"(r[3]) : "r"(a));
}
static __device__ __forceinline__ void mma16816(float* c, const uint32_t* a, const uint32_t* b) {
    asm volatile("mma.sync.aligned.m16n8k16.row.col.f32.f16.f16.f32 "
        "{%0,%1,%2,%3}, {%4,%5,%6,%7}, {%8,%9}, {%0,%1,%2,%3};"
        : "+f"(c[0]), "+f"(c[1]), "+f"(c[2]), "+f"(c[3])
        : "r"(a[0]), "r"(a[1]), "r"(a[2]), "r"(a[3]), "r"(b[0]), "r"(b[1]));
}
static __device__ __forceinline__ uint4 pack8(const float* src) {
    float4 v0 = *(const float4*)src, v1 = *(const float4*)(src + 4);
    __half2 a0 = __floats2half2_rn(v0.x, v0.y), a1 = __floats2half2_rn(v0.z, v0.w);
    __half2 a2 = __floats2half2_rn(v1.x, v1.y), a3 = __floats2half2_rn(v1.z, v1.w);
    uint4 pk;
    pk.x = *(uint32_t*)&a0; pk.y = *(uint32_t*)&a1;
    pk.z = *(uint32_t*)&a2; pk.w = *(uint32_t*)&a3;
    return pk;
}

__global__ void __launch_bounds__(256, 4)
tokenqkv_hmma_kernel(const float* __restrict__ xq_g,
                     const float* __restrict__ xs_g,
                     float* __restrict__ out)
{
    extern __shared__ char smc[];
    const uint32_t smb = smem_u32(smc);
    const int tid = threadIdx.x, lane = tid & 31, wid = tid >> 5;
    const int h = blockIdx.x, p = blockIdx.y, b = blockIdx.z;

    float* psum = (float*)(smc + SM_PSUM);   // [32][8]

    const float* xq  = xq_g + ((size_t)(b * P_ + p)) * HW_ * C_ + h * D_;
    const float* xsh = xs_g + (size_t)b * M_ * C_ + h * D_;

    // ---- stage kv fp16 (196x64 + pad to 208, SW128) ----
    {
        const int wrow = tid >> 3, seg = tid & 7;
        const uint32_t kb = (uint32_t)SM_KV + (uint32_t)wrow * 128 +
                            (uint32_t)((seg * 16) ^ ((wrow & 7) << 4));
        const float* srcb = xq + (size_t)wrow * C_ + seg * 8;
        #pragma unroll
        for (int k = 0; k < 6; k++)
            *(uint4*)(smc + kb + k * 4096) = pack8(srcb + (size_t)(32 * k) * C_);
        const int wt = 192 + wrow;
        if (wt < HW_)
            *(uint4*)(smc + kb + 6 * 4096) = pack8(srcb + (size_t)192 * C_);
        else if (wt < 208)
            *(uint4*)(smc + kb + 6 * 4096) = make_uint4(0, 0, 0, 0);
    }
    // ---- stage q fp16 (rows 0..31; >=25 zeroed) ----
    {
        const int qrow = tid >> 3, seg = tid & 7;
        const uint32_t qb = (uint32_t)SM_Q + (uint32_t)qrow * 128 +
                            (uint32_t)((seg * 16) ^ ((qrow & 7) << 4));
        if (qrow < M_)
            *(uint4*)(smc + qb) = pack8(xsh + (size_t)qrow * C_ + seg * 8);
        else
            *(uint4*)(smc + qb) = make_uint4(0, 0, 0, 0);
    }
    // ---- folded o_support copy ----
    if (h == 0 && p == 0) {
        const float4* src = (const float4*)(xs_g + (size_t)b * M_ * C_);
        float4* dst = (float4*)(out + (size_t)B_ * P_ * M_ * C_ + (size_t)b * M_ * C_);
        for (int i = tid; i < M_ * C_ / 4; i += 256) dst[i] = src[i];
    }
    __syncthreads();

    // ---- GEMM1: each warp owns BOTH m-halves x its n16-tiles (B loaded once) ----
    // warp 0..4 -> tiles {2w, 2w+1}; warp 5,6,7 -> tile {10,11,12}
    const int nb = (wid < 5) ? wid * 2 : 10 + (wid - 5);
    const int nt = (wid < 5) ? 2 : 1;

    float c1[2][2][2][4];   // [tile j][m-half][t(n8)][frag]
    #pragma unroll
    for (int j = 0; j < 2; j++)
        #pragma unroll
        for (int mh = 0; mh < 2; mh++)
            #pragma unroll
            for (int t = 0; t < 2; t++)
                { c1[j][mh][t][0] = c1[j][mh][t][1] = c1[j][mh][t][2] = c1[j][mh][t][3] = 0.0f; }

    {
        const int arow = lane & 15;
        const int acol = (lane >> 4) * 16;
        const int brow = ((lane >> 4) << 3) + (lane & 7);
        const int bcol = ((lane >> 3) & 1) * 16;
        #pragma unroll
        for (int ks = 0; ks < 4; ks++) {
            const int kb = ks * 32;
            uint32_t a0[4], a1[4];
            ldsm4(a0, smb + SM_Q + kvoff(arow, kb + acol));
            ldsm4(a1, smb + SM_Q + kvoff(16 + arow, kb + acol));
            #pragma unroll
            for (int j = 0; j < 2; j++) {
                if (j < nt) {
                    uint32_t bf[4];
                    ldsm4(bf, smb + SM_KV + kvoff((nb + j) * 16 + brow, kb + bcol));
                    mma16816(c1[j][0][0], a0, bf);
                    mma16816(c1[j][0][1], a0, bf + 2);
                    mma16816(c1[j][1][0], a1, bf);
                    mma16816(c1[j][1][1], a1, bf + 2);
                }
            }
        }
    }

    // ---- softmax (no max-subtraction); exp stored PERMUTED (validated R10):
    //      smem half-col s of a w16-tile holds w(s) = (s&1)|((s&2)<<2)|((s>>1)&6)
    {
        const int c2 = lane & 3;
        const __half2 z = __floats2half2_rn(0.0f, 0.0f);
        float sacc[2][2] = {{0.0f, 0.0f}, {0.0f, 0.0f}};   // [m-half][lo-row/hi-row]
        #pragma unroll
        for (int j = 0; j < 2; j++) if (j < nt) {
            const int tile = nb + j;
            const bool vlo = (tile < 12) | (c2 < 2);
            const bool vhi = (tile < 12);
            #pragma unroll
            for (int mh = 0; mh < 2; mh++) {
                const int rlo = mh * 16 + (lane >> 2);
                // row rlo (frag idx 0,1), t=0 and t=1
                {
                    __half2 lo = vlo ? __floats2half2_rn(__expf(c1[j][mh][0][0] * SCALE_),
                                                         __expf(c1[j][mh][0][1] * SCALE_)) : z;
                    __half2 hi = vhi ? __floats2half2_rn(__expf(c1[j][mh][1][0] * SCALE_),
                                                         __expf(c1[j][mh][1][1] * SCALE_)) : z;
                    float2 q = __half22float2(lo); sacc[mh][0] += q.x + q.y;
                    q = __half22float2(hi);        sacc[mh][0] += q.x + q.y;
                    uint2 pk; pk.x = *(uint32_t*)&lo; pk.y = *(uint32_t*)&hi;
                    *(uint2*)(smc + SM_EXP + rlo * EXSTR + tile * 32 + c2 * 8) = pk;
                }
                // row rlo+8 (frag idx 2,3)
                {
                    __half2 lo = vlo ? __floats2half2_rn(__expf(c1[j][mh][0][2] * SCALE_),
                                                         __expf(c1[j][mh][0][3] * SCALE_)) : z;
                    __half2 hi = vhi ? __floats2half2_rn(__expf(c1[j][mh][1][2] * SCALE_),
                                                         __expf(c1[j][mh][1][3] * SCALE_)) : z;
                    float2 q = __half22float2(lo); sacc[mh][1] += q.x + q.y;
                    q = __half22float2(hi);        sacc[mh][1] += q.x + q.y;
                    uint2 pk; pk.x = *(uint32_t*)&lo; pk.y = *(uint32_t*)&hi;
                    *(uint2*)(smc + SM_EXP + (rlo + 8) * EXSTR + tile * 32 + c2 * 8) = pk;
                }
            }
        }
        #pragma unroll
        for (int o = 1; o <= 2; o <<= 1) {
            sacc[0][0] += __shfl_xor_sync(0xffffffffu, sacc[0][0], o);
            sacc[0][1] += __shfl_xor_sync(0xffffffffu, sacc[0][1], o);
            sacc[1][0] += __shfl_xor_sync(0xffffffffu, sacc[1][0], o);
            sacc[1][1] += __shfl_xor_sync(0xffffffffu, sacc[1][1], o);
        }
        if ((lane & 3) == 0) {
            const int rq = lane >> 2;
            psum[rq * 8 + wid]        = sacc[0][0];
            psum[(rq + 8) * 8 + wid]  = sacc[0][1];
            psum[(rq + 16) * 8 + wid] = sacc[1][0];
            psum[(rq + 24) * 8 + wid] = sacc[1][1];
        }
    }
    __syncthreads();

    // ---- GEMM2: 8 warps (2 m-halves x 4 n16), kv rows re-permuted to match EXP ----
    {
        const int m0 = (wid >> 2) * 16;
        const int n0 = (wid & 3) * 16;
        float ca[4] = {0, 0, 0, 0}, cb[4] = {0, 0, 0, 0};
        const int arow = m0 + (lane & 15);
        const uint32_t abase = smb + SM_EXP + arow * EXSTR + (lane >> 4) * 16;
        const int s = lane & 15;
        const int wp = (s & 1) | ((s & 2) << 2) | ((s >> 1) & 6);
        const int bc = n0 * 2 + (lane >> 4) * 16;
        const uint32_t bb = smb + SM_KV + (uint32_t)(wp * 128) +
                            (uint32_t)(bc ^ ((wp & 7) << 4));
        #pragma unroll
        for (int kt = 0; kt < 13; kt++) {
            uint32_t a[4], bf[4];
            ldsm4(a, abase + kt * 32);
            ldsm4t(bf, bb + kt * 2048);
            mma16816(ca, a, bf);
            mma16816(cb, a, bf + 2);
        }

        // epilogue: scale by 1/sum (8 partials), direct STG.64
        const int rr0 = m0 + (lane >> 2), rr1 = rr0 + 8;
        const int cc = n0 + (lane & 3) * 2;
        const size_t ob = ((size_t)(b * P_ + p) * M_) * C_ + h * D_;
        {
            float4 pa = *(float4*)&psum[rr0 * 8];
            float4 pbv = *(float4*)&psum[rr0 * 8 + 4];
            float iv = 1.0f / (pa.x + pa.y + pa.z + pa.w + pbv.x + pbv.y + pbv.z + pbv.w);
            if (rr0 < M_) {
                float* o0 = out + ob + (size_t)rr0 * C_ + cc;
                *(float2*)o0       = make_float2(ca[0] * iv, ca[1] * iv);
                *(float2*)(o0 + 8) = make_float2(cb[0] * iv, cb[1] * iv);
            }
        }
        if (rr1 < M_) {
            float4 pa = *(float4*)&psum[rr1 * 8];
            float4 pbv = *(float4*)&psum[rr1 * 8 + 4];
            float iv = 1.0f / (pa.x + pa.y + pa.z + pa.w + pbv.x + pbv.y + pbv.z + pbv.w);
            float* o1 = out + ob + (size_t)rr1 * C_ + cc;
            *(float2*)o1       = make_float2(ca[2] * iv, ca[3] * iv);
            *(float2*)(o1 + 8) = make_float2(cb[2] * iv, cb[3] * iv);
        }
    }
}

extern "C" void kernel_launch(void* const* d_in, const int* in_sizes, int n_in,
                              void* d_out, int out_size) {
    const float* xq = (const float*)d_in[0];   // (8,5,15,196,384)
    const float* xs = (const float*)d_in[1];   // (8,25,384)
    float* out = (float*)d_out;

    cudaFuncSetAttribute(tokenqkv_hmma_kernel,
                         cudaFuncAttributeMaxDynamicSharedMemorySize, SMEM_BYTES);

    dim3 grid(H_, P_, B_);
    tokenqkv_hmma_kernel<<<grid, 256, SMEM_BYTES>>>(xq, xs, out);
}

// round 12
// speedup vs baseline: 1.0072x; 1.0072x over previous
#include <cuda_runtime.h>
#include <cuda_fp16.h>
#include <cstdint>

#define B_ 8
#define P_ 75
#define HW_ 196
#define C_ 384
#define H_ 6
#define D_ 64
#define M_ 25
#define SCALE_ 0.125f

// smem byte map
#define SM_KV   0          // 208 rows x 128B fp16, SW128 swizzled
#define SM_Q    26624      // 32 rows x 128B fp16, swizzled
#define SM_EXP  30720      // 32 rows x 432B (216 fp16, padded stride; w-permuted cols)
#define SM_PSUM 44544      // 32 rows x 4 f32
#define SMEM_BYTES 45056

#define EXSTR 432

static __device__ __forceinline__ uint32_t kvoff(int r, int c) {   // 128B-row SW128
    return (uint32_t)(r * 128 + ((c) ^ ((r & 7) << 4)));
}
static __device__ __forceinline__ uint32_t smem_u32(const void* p) {
    uint32_t a;
    asm("{ .reg .u64 t; cvta.to.shared.u64 t, %1; cvt.u32.u64 %0, t; }" : "=r"(a) : "l"(p));
    return a;
}
static __device__ __forceinline__ void ldsm4(uint32_t* r, uint32_t a) {
    asm volatile("ldmatrix.sync.aligned.m8n8.x4.shared.b16 {%0,%1,%2,%3}, [%4];"
        : "=r"(r[0]), "=r"(r[1]), "=r"(r[2]), "=r"(r[3]) : "r"(a));
}
static __device__ __forceinline__ void ldsm4t(uint32_t* r, uint32_t a) {
    asm volatile("ldmatrix.sync.aligned.m8n8.x4.trans.shared.b16 {%0,%1,%2,%3}, [%4];"
        : "=r"(r[0]), "=r"(r[1]), "=r"(r[2]), "=r"(r[3]) : "r"(a));
}
static __device__ __forceinline__ void mma16816(float* c, const uint32_t* a, const uint32_t* b) {
    asm volatile("mma.sync.aligned.m16n8k16.row.col.f32.f16.f16.f32 "
        "{%0,%1,%2,%3}, {%4,%5,%6,%7}, {%8,%9}, {%0,%1,%2,%3};"
        : "+f"(c[0]), "+f"(c[1]), "+f"(c[2]), "+f"(c[3])
        : "r"(a[0]), "r"(a[1]), "r"(a[2]), "r"(a[3]), "r"(b[0]), "r"(b[1]));
}
static __device__ __forceinline__ uint4 pack8(const float* src) {
    float4 v0 = *(const float4*)src, v1 = *(const float4*)(src + 4);
    __half2 a0 = __floats2half2_rn(v0.x, v0.y), a1 = __floats2half2_rn(v0.z, v0.w);
    __half2 a2 = __floats2half2_rn(v1.x, v1.y), a3 = __floats2half2_rn(v1.z, v1.w);
    uint4 pk;
    pk.x = *(uint32_t*)&a0; pk.y = *(uint32_t*)&a1;
    pk.z = *(uint32_t*)&a2; pk.w = *(uint32_t*)&a3;
    return pk;
}

__global__ void __launch_bounds__(256, 4)
tokenqkv_hmma_kernel(const float* __restrict__ xq_g,
                     const float* __restrict__ xs_g,
                     float* __restrict__ out)
{
    extern __shared__ char smc[];
    const uint32_t smb = smem_u32(smc);
    const int tid = threadIdx.x, lane = tid & 31, wid = tid >> 5;
    const int h = blockIdx.x, p = blockIdx.y, b = blockIdx.z;

    float* psum = (float*)(smc + SM_PSUM);

    const float* xq  = xq_g + ((size_t)(b * P_ + p)) * HW_ * C_ + h * D_;
    const float* xsh = xs_g + (size_t)b * M_ * C_ + h * D_;

    // ---- stage kv fp16 (196x64 + pad to 208, SW128) ----
    {
        const int wrow = tid >> 3, seg = tid & 7;
        const uint32_t kb = (uint32_t)SM_KV + (uint32_t)wrow * 128 +
                            (uint32_t)((seg * 16) ^ ((wrow & 7) << 4));
        const float* srcb = xq + (size_t)wrow * C_ + seg * 8;
        #pragma unroll
        for (int k = 0; k < 6; k++)
            *(uint4*)(smc + kb + k * 4096) = pack8(srcb + (size_t)(32 * k) * C_);
        const int wt = 192 + wrow;
        if (wt < HW_)
            *(uint4*)(smc + kb + 6 * 4096) = pack8(srcb + (size_t)192 * C_);
        else if (wt < 208)
            *(uint4*)(smc + kb + 6 * 4096) = make_uint4(0, 0, 0, 0);
    }
    // ---- stage q fp16 (rows 0..31; >=25 zeroed): exactly 256 threads ----
    {
        const int qrow = tid >> 3, seg = tid & 7;
        const uint32_t qb = (uint32_t)SM_Q + (uint32_t)qrow * 128 +
                            (uint32_t)((seg * 16) ^ ((qrow & 7) << 4));
        if (qrow < M_)
            *(uint4*)(smc + qb) = pack8(xsh + (size_t)qrow * C_ + seg * 8);
        else
            *(uint4*)(smc + qb) = make_uint4(0, 0, 0, 0);
    }
    // ---- folded o_support copy ----
    if (h == 0 && p == 0) {
        const float4* src = (const float4*)(xs_g + (size_t)b * M_ * C_);
        float4* dst = (float4*)(out + (size_t)B_ * P_ * M_ * C_ + (size_t)b * M_ * C_);
        for (int i = tid; i < M_ * C_ / 4; i += 256) dst[i] = src[i];
    }
    __syncthreads();

    // ---- GEMM1: logits[m 0..31][w 0..207] in register fragments (R9 layout) ----
    const int m0 = (wid >> 2) * 16;
    const int ngrp = wid & 3;
    const int pb = (ngrp == 0) ? 0 : 4 + (ngrp - 1) * 3;   // n16-tiles {0-3},{4-6},{7-9},{10-12}
    const int np = (ngrp == 0) ? 4 : 3;

    float c1[4][2][4];
    #pragma unroll
    for (int j = 0; j < 4; j++)
        #pragma unroll
        for (int t = 0; t < 2; t++)
            { c1[j][t][0] = c1[j][t][1] = c1[j][t][2] = c1[j][t][3] = 0.0f; }

    {
        const int arow = m0 + (lane & 15);
        const int acol = (lane >> 4) * 16;
        const int brow = ((lane >> 4) << 3) + (lane & 7);
        const int bcol = ((lane >> 3) & 1) * 16;
        #pragma unroll
        for (int ks = 0; ks < 4; ks++) {
            const int kb = ks * 32;
            uint32_t a[4];
            ldsm4(a, smb + SM_Q + kvoff(arow, kb + acol));
            #pragma unroll
            for (int j = 0; j < 4; j++) {
                if (j < np) {
                    uint32_t bf[4];
                    ldsm4(bf, smb + SM_KV + kvoff((pb + j) * 16 + brow, kb + bcol));
                    mma16816(c1[j][0], a, bf);
                    mma16816(c1[j][1], a, bf + 2);
                }
            }
        }
    }

    // ---- softmax (no max-subtraction); exp stored PERMUTED (validated R10/R11):
    //      smem half-col s of a w16-tile holds w(s) = (s&1)|((s&2)<<2)|((s>>1)&6)
    const int r0 = m0 + (lane >> 2), r1 = r0 + 8;
    {
        const int c2 = lane & 3;
        const __half2 z = __floats2half2_rn(0.0f, 0.0f);
        float s0 = 0.0f, s1 = 0.0f;
        #pragma unroll
        for (int j = 0; j < 4; j++) if (j < np) {
            const int tile = pb + j;
            const bool vlo = (tile < 12) | (c2 < 2);
            const bool vhi = (tile < 12);
            // row r0 (frag idx 0,1)
            {
                __half2 lo = vlo ? __floats2half2_rn(__expf(c1[j][0][0] * SCALE_),
                                                     __expf(c1[j][0][1] * SCALE_)) : z;
                __half2 hi = vhi ? __floats2half2_rn(__expf(c1[j][1][0] * SCALE_),
                                                     __expf(c1[j][1][1] * SCALE_)) : z;
                float2 q = __half22float2(lo); s0 += q.x + q.y;
                q = __half22float2(hi);        s0 += q.x + q.y;
                uint2 pk; pk.x = *(uint32_t*)&lo; pk.y = *(uint32_t*)&hi;
                *(uint2*)(smc + SM_EXP + r0 * EXSTR + tile * 32 + c2 * 8) = pk;
            }
            // row r1 (frag idx 2,3)
            {
                __half2 lo = vlo ? __floats2half2_rn(__expf(c1[j][0][2] * SCALE_),
                                                     __expf(c1[j][0][3] * SCALE_)) : z;
                __half2 hi = vhi ? __floats2half2_rn(__expf(c1[j][1][2] * SCALE_),
                                                     __expf(c1[j][1][3] * SCALE_)) : z;
                float2 q = __half22float2(lo); s1 += q.x + q.y;
                q = __half22float2(hi);        s1 += q.x + q.y;
                uint2 pk; pk.x = *(uint32_t*)&lo; pk.y = *(uint32_t*)&hi;
                *(uint2*)(smc + SM_EXP + r1 * EXSTR + tile * 32 + c2 * 8) = pk;
            }
        }
        #pragma unroll
        for (int o = 1; o <= 2; o <<= 1) {
            s0 += __shfl_xor_sync(0xffffffffu, s0, o);
            s1 += __shfl_xor_sync(0xffffffffu, s1, o);
        }
        if ((lane & 3) == 0) { psum[r0 * 4 + ngrp] = s0; psum[r1 * 4 + ngrp] = s1; }
    }
    __syncthreads();

    // ---- GEMM2: 8 warps (2 m-halves x 4 n16), kv rows re-permuted to match EXP ----
    {
        const int n0 = ngrp * 16;
        float ca[4] = {0, 0, 0, 0}, cb[4] = {0, 0, 0, 0};
        const int arow = m0 + (lane & 15);
        const uint32_t abase = smb + SM_EXP + arow * EXSTR + (lane >> 4) * 16;
        const int s = lane & 15;
        const int wp = (s & 1) | ((s & 2) << 2) | ((s >> 1) & 6);
        const int bc = n0 * 2 + (lane >> 4) * 16;
        const uint32_t bb = smb + SM_KV + (uint32_t)(wp * 128) +
                            (uint32_t)(bc ^ ((wp & 7) << 4));
        #pragma unroll
        for (int kt = 0; kt < 13; kt++) {
            uint32_t a[4], bf[4];
            ldsm4(a, abase + kt * 32);
            ldsm4t(bf, bb + kt * 2048);
            mma16816(ca, a, bf);
            mma16816(cb, a, bf + 2);
        }

        // epilogue: scale by 1/sum, direct STG.64
        const int cc = n0 + (lane & 3) * 2;
        const size_t ob = ((size_t)(b * P_ + p) * M_) * C_ + h * D_;
        float4 ps0 = *(float4*)&psum[r0 * 4];
        float i0 = 1.0f / (ps0.x + ps0.y + ps0.z + ps0.w);
        if (r0 < M_) {
            float* o0 = out + ob + (size_t)r0 * C_ + cc;
            *(float2*)o0       = make_float2(ca[0] * i0, ca[1] * i0);
            *(float2*)(o0 + 8) = make_float2(cb[0] * i0, cb[1] * i0);
        }
        if (r1 < M_) {
            float4 ps1 = *(float4*)&psum[r1 * 4];
            float i1 = 1.0f / (ps1.x + ps1.y + ps1.z + ps1.w);
            float* o1 = out + ob + (size_t)r1 * C_ + cc;
            *(float2*)o1       = make_float2(ca[2] * i1, ca[3] * i1);
            *(float2*)(o1 + 8) = make_float2(cb[2] * i1, cb[3] * i1);
        }
    }
}

extern "C" void kernel_launch(void* const* d_in, const int* in_sizes, int n_in,
                              void* d_out, int out_size) {
    const float* xq = (const float*)d_in[0];   // (8,5,15,196,384)
    const float* xs = (const float*)d_in[1];   // (8,25,384)
    float* out = (float*)d_out;

    cudaFuncSetAttribute(tokenqkv_hmma_kernel,
                         cudaFuncAttributeMaxDynamicSharedMemorySize, SMEM_BYTES);

    dim3 grid(H_, P_, B_);
    tokenqkv_hmma_kernel<<<grid, 256, SMEM_BYTES>>>(xq, xs, out);
}

// round 13
// speedup vs baseline: 1.1141x; 1.1060x over previous
#include <cuda_runtime.h>
#include <cuda_fp16.h>
#include <cstdint>

#define B_ 8
#define P_ 75
#define HW_ 196
#define C_ 384
#define H_ 6
#define D_ 64
#define M_ 25
// SCALE * log2(e) = 0.125 * 1.4426950408889634
#define SC_LOG2E 0.18033688011112043f

// smem byte map
#define SM_KV   0          // 208 rows x 128B fp16, SW128 swizzled
#define SM_Q    26624      // 32 rows x 128B fp16, swizzled
#define SM_EXP  30720      // 32 rows x 432B (216 fp16, padded stride)
#define SM_PSUM 44544      // 32 rows x 4 f32
#define SMEM_BYTES 45056

#define EXSTR 432

static __device__ __forceinline__ uint32_t kvoff(int r, int c) {   // 128B-row SW128
    return (uint32_t)(r * 128 + ((c) ^ ((r & 7) << 4)));
}
static __device__ __forceinline__ uint32_t smem_u32(const void* p) {
    uint32_t a;
    asm("{ .reg .u64 t; cvta.to.shared.u64 t, %1; cvt.u32.u64 %0, t; }" : "=r"(a) : "l"(p));
    return a;
}
static __device__ __forceinline__ void ldsm4(uint32_t* r, uint32_t a) {
    asm volatile("ldmatrix.sync.aligned.m8n8.x4.shared.b16 {%0,%1,%2,%3}, [%4];"
        : "=r"(r[0]), "=r"(r[1]), "=r"(r[2]), "=r"(r[3]) : "r"(a));
}
static __device__ __forceinline__ void ldsm4t(uint32_t* r, uint32_t a) {
    asm volatile("ldmatrix.sync.aligned.m8n8.x4.trans.shared.b16 {%0,%1,%2,%3}, [%4];"
        : "=r"(r[0]), "=r"(r[1]), "=r"(r[2]), "=r"(r[3]) : "r"(a));
}
static __device__ __forceinline__ void mma16816(float* c, const uint32_t* a, const uint32_t* b) {
    asm volatile("mma.sync.aligned.m16n8k16.row.col.f32.f16.f16.f32 "
        "{%0,%1,%2,%3}, {%4,%5,%6,%7}, {%8,%9}, {%0,%1,%2,%3};"
        : "+f"(c[0]), "+f"(c[1]), "+f"(c[2]), "+f"(c[3])
        : "r"(a[0]), "r"(a[1]), "r"(a[2]), "r"(a[3]), "r"(b[0]), "r"(b[1]));
}
static __device__ __forceinline__ uint4 pack8(const float* src) {
    float4 v0 = *(const float4*)src, v1 = *(const float4*)(src + 4);
    __half2 a0 = __floats2half2_rn(v0.x, v0.y), a1 = __floats2half2_rn(v0.z, v0.w);
    __half2 a2 = __floats2half2_rn(v1.x, v1.y), a3 = __floats2half2_rn(v1.z, v1.w);
    uint4 pk;
    pk.x = *(uint32_t*)&a0; pk.y = *(uint32_t*)&a1;
    pk.z = *(uint32_t*)&a2; pk.w = *(uint32_t*)&a3;
    return pk;
}

__global__ void __launch_bounds__(256, 4)
tokenqkv_hmma_kernel(const float* __restrict__ xq_g,
                     const float* __restrict__ xs_g,
                     float* __restrict__ out)
{
    extern __shared__ char smc[];
    const uint32_t smb = smem_u32(smc);
    const int tid = threadIdx.x, lane = tid & 31, wid = tid >> 5;
    const int h = blockIdx.x, p = blockIdx.y, b = blockIdx.z;

    float* psum = (float*)(smc + SM_PSUM);

    const float* xq  = xq_g + ((size_t)(b * P_ + p)) * HW_ * C_ + h * D_;
    const float* xsh = xs_g + (size_t)b * M_ * C_ + h * D_;

    // ---- stage kv fp16 (196x64 + pad to 208, SW128) ----
    {
        const int wrow = tid >> 3, seg = tid & 7;
        const uint32_t kb = (uint32_t)SM_KV + (uint32_t)wrow * 128 +
                            (uint32_t)((seg * 16) ^ ((wrow & 7) << 4));
        const float* srcb = xq + (size_t)wrow * C_ + seg * 8;
        #pragma unroll
        for (int k = 0; k < 6; k++)
            *(uint4*)(smc + kb + k * 4096) = pack8(srcb + (size_t)(32 * k) * C_);
        const int wt = 192 + wrow;
        if (wt < HW_)
            *(uint4*)(smc + kb + 6 * 4096) = pack8(srcb + (size_t)192 * C_);
        else if (wt < 208)
            *(uint4*)(smc + kb + 6 * 4096) = make_uint4(0, 0, 0, 0);
    }
    // ---- stage q fp16 (rows 0..31; >=25 zeroed): exactly 256 threads ----
    {
        const int qrow = tid >> 3, seg = tid & 7;
        const uint32_t qb = (uint32_t)SM_Q + (uint32_t)qrow * 128 +
                            (uint32_t)((seg * 16) ^ ((qrow & 7) << 4));
        if (qrow < M_)
            *(uint4*)(smc + qb) = pack8(xsh + (size_t)qrow * C_ + seg * 8);
        else
            *(uint4*)(smc + qb) = make_uint4(0, 0, 0, 0);
    }
    // ---- folded o_support copy ----
    if (h == 0 && p == 0) {
        const float4* src = (const float4*)(xs_g + (size_t)b * M_ * C_);
        float4* dst = (float4*)(out + (size_t)B_ * P_ * M_ * C_ + (size_t)b * M_ * C_);
        for (int i = tid; i < M_ * C_ / 4; i += 256) dst[i] = src[i];
    }
    __syncthreads();

    // ---- GEMM1: logits[m 0..31][w 0..207] in register fragments ----
    const int m0 = (wid >> 2) * 16;
    const int ngrp = wid & 3;
    const int pb = (ngrp == 0) ? 0 : 4 + (ngrp - 1) * 3;   // n16-tiles {0-3},{4-6},{7-9},{10-12}
    const int np = (ngrp == 0) ? 4 : 3;

    float c1[4][2][4];
    #pragma unroll
    for (int j = 0; j < 4; j++)
        #pragma unroll
        for (int t = 0; t < 2; t++)
            { c1[j][t][0] = c1[j][t][1] = c1[j][t][2] = c1[j][t][3] = 0.0f; }

    {
        const int arow = m0 + (lane & 15);
        const int acol = (lane >> 4) * 16;
        const int brow = ((lane >> 4) << 3) + (lane & 7);
        const int bcol = ((lane >> 3) & 1) * 16;
        #pragma unroll
        for (int ks = 0; ks < 4; ks++) {
            const int kb = ks * 32;
            uint32_t a[4];
            ldsm4(a, smb + SM_Q + kvoff(arow, kb + acol));
            #pragma unroll
            for (int j = 0; j < 4; j++) {
                if (j < np) {
                    uint32_t bf[4];
                    ldsm4(bf, smb + SM_KV + kvoff((pb + j) * 16 + brow, kb + bcol));
                    mma16816(c1[j][0], a, bf);
                    mma16816(c1[j][1], a, bf + 2);
                }
            }
        }
    }

    // ---- softmax (no max-subtraction): exp(x*s) = exp2(x*s*log2e), 1 FMUL+MUFU ----
    const int r0 = m0 + (lane >> 2), r1 = r0 + 8;
    {
        float s0 = 0.0f, s1 = 0.0f;
        #pragma unroll
        for (int j = 0; j < 4; j++) if (j < np)
            #pragma unroll
            for (int t = 0; t < 2; t++) {
                const int col = (pb + j) * 16 + t * 8 + (lane & 3) * 2;
                const bool valid = (col < HW_);
                __half2 hh = __floats2half2_rn(0.0f, 0.0f);
                if (valid) {
                    hh = __floats2half2_rn(exp2f(c1[j][t][0] * SC_LOG2E),
                                           exp2f(c1[j][t][1] * SC_LOG2E));
                    float2 q2 = __half22float2(hh);
                    s0 += q2.x + q2.y;
                }
                *(__half2*)(smc + SM_EXP + r0 * EXSTR + col * 2) = hh;
                __half2 hh1 = __floats2half2_rn(0.0f, 0.0f);
                if (valid) {
                    hh1 = __floats2half2_rn(exp2f(c1[j][t][2] * SC_LOG2E),
                                            exp2f(c1[j][t][3] * SC_LOG2E));
                    float2 q2 = __half22float2(hh1);
                    s1 += q2.x + q2.y;
                }
                *(__half2*)(smc + SM_EXP + r1 * EXSTR + col * 2) = hh1;
            }
        #pragma unroll
        for (int o = 1; o <= 2; o <<= 1) {
            s0 += __shfl_xor_sync(0xffffffffu, s0, o);
            s1 += __shfl_xor_sync(0xffffffffu, s1, o);
        }
        if ((lane & 3) == 0) { psum[r0 * 4 + ngrp] = s0; psum[r1 * 4 + ngrp] = s1; }
    }
    // Per-half barrier: GEMM2 warp (m-half mh = wid>>2) consumes only EXP rows
    // mh*16..mh*16+31 and psum of those rows, produced solely by the 4 warps of
    // the same half (tids mh*128..mh*128+127). No cross-half dependency.
    if (tid < 128) { asm volatile("bar.sync 3, 128;" ::: "memory"); }
    else           { asm volatile("bar.sync 4, 128;" ::: "memory"); }

    // ---- GEMM2: 8 warps (2 m-halves x 4 n16), direct STG epilogue ----
    {
        const int n0 = ngrp * 16;
        float ca[4] = {0, 0, 0, 0}, cb[4] = {0, 0, 0, 0};
        const int arow = m0 + (lane & 15);
        const uint32_t abase = smb + SM_EXP + arow * EXSTR + (lane >> 4) * 16;
        const int brow = lane & 15;
        const int bcol = n0 * 2 + (lane >> 4) * 16;        // bytes
        #pragma unroll
        for (int kt = 0; kt < 13; kt++) {
            const int k = kt * 16;
            uint32_t a[4], bf[4];
            ldsm4(a, abase + kt * 32);
            ldsm4t(bf, smb + SM_KV + kvoff(k + brow, bcol));
            mma16816(ca, a, bf);
            mma16816(cb, a, bf + 2);
        }

        // epilogue: scale by 1/sum, write STG.64 directly
        const int cc = n0 + (lane & 3) * 2;
        const size_t ob = ((size_t)(b * P_ + p) * M_) * C_ + h * D_;
        float4 ps0 = *(float4*)&psum[r0 * 4];
        float i0 = 1.0f / (ps0.x + ps0.y + ps0.z + ps0.w);
        if (r0 < M_) {
            float* o0 = out + ob + (size_t)r0 * C_ + cc;
            *(float2*)o0       = make_float2(ca[0] * i0, ca[1] * i0);
            *(float2*)(o0 + 8) = make_float2(cb[0] * i0, cb[1] * i0);
        }
        if (r1 < M_) {
            float4 ps1 = *(float4*)&psum[r1 * 4];
            float i1 = 1.0f / (ps1.x + ps1.y + ps1.z + ps1.w);
            float* o1 = out + ob + (size_t)r1 * C_ + cc;
            *(float2*)o1       = make_float2(ca[2] * i1, ca[3] * i1);
            *(float2*)(o1 + 8) = make_float2(cb[2] * i1, cb[3] * i1);
        }
    }
}

extern "C" void kernel_launch(void* const* d_in, const int* in_sizes, int n_in,
                              void* d_out, int out_size) {
    const float* xq = (const float*)d_in[0];   // (8,5,15,196,384)
    const float* xs = (const float*)d_in[1];   // (8,25,384)
    float* out = (float*)d_out;

    cudaFuncSetAttribute(tokenqkv_hmma_kernel,
                         cudaFuncAttributeMaxDynamicSharedMemorySize, SMEM_BYTES);

    dim3 grid(H_, P_, B_);
    tokenqkv_hmma_kernel<<<grid, 256, SMEM_BYTES>>>(xq, xs, out);
}